// round 5
// baseline (speedup 1.0000x reference)
#include <cuda_runtime.h>

#define NB 4
#define NT 1024
#define NTOK (NB * NT)     // 4096
#define NL 64
#define NC 256
#define HALF 256
#define VD 512

// Cross-block output accumulator (zero-initialized at module load; each launch
// leaves it zeroed again via atomicExch drain). 4*256 floats = 4 KB.
__device__ float g_acc[NB * NC];
__device__ int   g_cnt;           // arrival counter, likewise self-resetting

__global__ __launch_bounds__(256, 1)
void fused_kernel(const int*   __restrict__ indices,
                  const float* __restrict__ scores,
                  const float* __restrict__ W,
                  const int*   __restrict__ label,
                  const int*   __restrict__ idxp,
                  const float* __restrict__ weight,
                  float*       __restrict__ out) {
    __shared__ int   s_tok[NTOK];          // 16 KB worst case: all tokens one label
    __shared__ int   s_m;
    __shared__ float su[NB * HALF];        // u[b][d], 4 KB
    __shared__ int   s_last;

    const int l   = blockIdx.x;
    const int tid = threadIdx.x;
    const int off = (idxp[0] == 1) ? HALF : 0;

    // ---- Phase 1a: scan tokens, build match list in smem ----
    if (tid == 0) s_m = 0;
    __syncthreads();
    #pragma unroll
    for (int t = tid; t < NTOK; t += 256) {
        if (__ldg(label + t) == l) {
            int p = atomicAdd(&s_m, 1);
            s_tok[p] = t;
        }
    }
    __syncthreads();
    const int m = s_m;

    // ---- Phase 1b: u[b][tid] = sum over matched tokens of s * weight[idx, off+tid] ----
    float a0 = 0.f, a1 = 0.f, a2 = 0.f, a3 = 0.f;
    #pragma unroll 4
    for (int i = 0; i < m; i++) {
        int   t   = s_tok[i];
        int   idx = __ldg(indices + t);
        float s   = __ldg(scores + t);
        int   b   = t >> 10;               // T = 1024
        float w   = __ldg(weight + (size_t)idx * VD + off + tid);
        float v   = s * w;
        a0 += (b == 0) ? v : 0.f;
        a1 += (b == 1) ? v : 0.f;
        a2 += (b == 2) ? v : 0.f;
        a3 += (b == 3) ? v : 0.f;
    }
    su[0 * HALF + tid] = a0;
    su[1 * HALF + tid] = a1;
    su[2 * HALF + tid] = a2;
    su[3 * HALF + tid] = a3;
    __syncthreads();

    // ---- Phase 2: partial_out[b][c=tid] = sum_d su[b][d] * W[l, off+d, c] ----
    const float* wp = W + ((size_t)l * VD + off) * NC + tid;
    float c0 = 0.f, c1 = 0.f, c2 = 0.f, c3 = 0.f;
    #pragma unroll 8
    for (int d = 0; d < HALF; d++) {
        float w = __ldg(wp);
        wp += NC;
        c0 += su[0 * HALF + d] * w;
        c1 += su[1 * HALF + d] * w;
        c2 += su[2 * HALF + d] * w;
        c3 += su[3 * HALF + d] * w;
    }
    atomicAdd(g_acc + 0 * NC + tid, c0);
    atomicAdd(g_acc + 1 * NC + tid, c1);
    atomicAdd(g_acc + 2 * NC + tid, c2);
    atomicAdd(g_acc + 3 * NC + tid, c3);

    // ---- Phase 3: last-arriving block drains the accumulator ----
    __syncthreads();
    if (tid == 0) {
        __threadfence();                    // publish our atomics before counting
        int old = atomicAdd(&g_cnt, 1);
        s_last = (old == NL - 1);
    }
    __syncthreads();
    if (s_last) {
        __threadfence();                    // acquire all blocks' contributions
        #pragma unroll
        for (int b = 0; b < NB; b++) {
            int i = b * NC + tid;
            float v = atomicExch(g_acc + i, 0.f);   // read + reset for next replay
            out[i] = v;
        }
        if (tid == 0) atomicExch(&g_cnt, 0);        // reset counter for next replay
    }
}

extern "C" void kernel_launch(void* const* d_in, const int* in_sizes, int n_in,
                              void* d_out, int out_size) {
    const int*   indices = (const int*)  d_in[0];
    const float* scores  = (const float*)d_in[1];
    const float* W       = (const float*)d_in[2];
    const int*   label   = (const int*)  d_in[3];
    const int*   index   = (const int*)  d_in[4];
    const float* weight  = (const float*)d_in[5];
    float* out = (float*)d_out;

    fused_kernel<<<NL, 256>>>(indices, scores, W, label, index, weight, out);
}